// round 7
// baseline (speedup 1.0000x reference)
#include <cuda_runtime.h>

#define N_NODES 50000
#define R_REL 51
#define F_DIM 32
#define E_DIM 32
#define C_DIM 16
#define B_BASES 30
#define NNZ_MAX 2001024

typedef unsigned long long ull;

// ---- scratch (__device__ globals: no allocation allowed) -------------------
__device__ float g_w1[R_REL * F_DIM * E_DIM];            // [r][f][e]  208 KB
__device__ float g_w2[R_REL * E_DIM * C_DIM];            // [r][h][c]  104 KB
__device__ __align__(16) float g_h1[N_NODES * E_DIM];    // 6.4 MB
__device__ unsigned g_hist[R_REL];
__device__ unsigned g_cursor[R_REL];
__device__ unsigned g_done;
__device__ unsigned g_nm[NNZ_MAX];                       // (n<<16)|m (both <65536)
__device__ float    g_v[NNZ_MAX];
__device__ unsigned char g_r[NNZ_MAX];

// ---- packed f32x2 helpers --------------------------------------------------
__device__ __forceinline__ ull pack2(float lo, float hi) {
    ull r; asm("mov.b64 %0,{%1,%2};" : "=l"(r) : "f"(lo), "f"(hi)); return r;
}
__device__ __forceinline__ void unpack2(ull v, float& lo, float& hi) {
    asm("mov.b64 {%0,%1},%2;" : "=f"(lo), "=f"(hi) : "l"(v));
}
__device__ __forceinline__ ull ffma2(ull a, ull b, ull c) {
    ull d; asm("fma.rn.f32x2 %0,%1,%2,%3;" : "=l"(d) : "l"(a), "l"(b), "l"(c)); return d;
}
__device__ __forceinline__ ull fmul2(ull a, ull b) {
    ull d; asm("mul.rn.f32x2 %0,%1,%2;" : "=l"(d) : "l"(a), "l"(b)); return d;
}
__device__ __forceinline__ void red_add_v4(float* p, float a, float b, float c, float d) {
    asm volatile("red.global.add.v4.f32 [%0], {%1,%2,%3,%4};"
                 :: "l"(p), "f"(a), "f"(b), "f"(c), "f"(d) : "memory");
}
__device__ __forceinline__ float f4c(const float4& v, int c) {
    return c == 0 ? v.x : c == 1 ? v.y : c == 2 ? v.z : v.w;
}

// ---------------------------------------------------------------------------
// Fused: per-relation weights + zero g_hist/g_done + zero g_h1.
// ---------------------------------------------------------------------------
__global__ void compute_w_kernel(const float* __restrict__ comps1,
                                 const float* __restrict__ bases1,
                                 const float* __restrict__ comps2,
                                 const float* __restrict__ bases2) {
    int idx = blockIdx.x * blockDim.x + threadIdx.x;
    const int total1 = R_REL * F_DIM * E_DIM;
    const int total2 = R_REL * E_DIM * C_DIM;
    if (idx < total1) {
        int r = idx / (F_DIM * E_DIM);
        int fe = idx - r * (F_DIM * E_DIM);
        float acc = 0.f;
#pragma unroll
        for (int b = 0; b < B_BASES; b++)
            acc = fmaf(comps1[r * B_BASES + b], bases1[b * (F_DIM * E_DIM) + fe], acc);
        g_w1[idx] = acc;
    }
    if (idx < total2) {
        int r = idx / (E_DIM * C_DIM);
        int hc = idx - r * (E_DIM * C_DIM);
        float acc = 0.f;
#pragma unroll
        for (int b = 0; b < B_BASES; b++)
            acc = fmaf(comps2[r * B_BASES + b], bases2[b * (E_DIM * C_DIM) + hc], acc);
        g_w2[idx] = acc;
    }
    if (idx < R_REL) g_hist[idx] = 0;
    if (idx == 0) g_done = 0;
    // zero h1 (float4 grid-stride)
    float4* h4 = (float4*)g_h1;
    const int nh4 = N_NODES * E_DIM / 4;
    for (int i = idx; i < nh4; i += gridDim.x * blockDim.x)
        h4[i] = make_float4(0.f, 0.f, 0.f, 0.f);
}

// ---------------------------------------------------------------------------
// Fused: histogram + (last block) exclusive scan -> g_cursor, + init out=bias2.
// ---------------------------------------------------------------------------
__global__ void hist_kernel(const int* __restrict__ rows, int nnz,
                            float* __restrict__ out,
                            const float* __restrict__ bias2) {
    __shared__ unsigned sh[R_REL];
    if (threadIdx.x < R_REL) sh[threadIdx.x] = 0;
    __syncthreads();
    int gsz = gridDim.x * blockDim.x;
    for (int e = blockIdx.x * blockDim.x + threadIdx.x; e < nnz; e += gsz)
        atomicAdd(&sh[(unsigned)rows[e] / N_NODES], 1u);
    // init out with bias2 while we're here (independent work)
    for (int i = blockIdx.x * blockDim.x + threadIdx.x; i < N_NODES * C_DIM; i += gsz)
        out[i] = bias2[i & (C_DIM - 1)];
    __syncthreads();
    if (threadIdx.x < R_REL) atomicAdd(&g_hist[threadIdx.x], sh[threadIdx.x]);
    __threadfence();
    __syncthreads();
    if (threadIdx.x == 0) {
        unsigned t = atomicAdd(&g_done, 1u);
        if (t == gridDim.x - 1) {               // last block: scan
            unsigned s = 0;
            for (int r = 0; r < R_REL; r++) { g_cursor[r] = s; s += g_hist[r]; }
        }
    }
}

// Block-aggregated scatter into relation buckets.
#define SCATTER_CHUNK 8192
__global__ void scatter_kernel(const int* __restrict__ rows,
                               const int* __restrict__ cols,
                               const float* __restrict__ vals, int nnz) {
    __shared__ unsigned cnt[R_REL];
    __shared__ unsigned base[R_REL];
    int start = blockIdx.x * SCATTER_CHUNK;
    if (start >= nnz) return;
    int end = min(start + SCATTER_CHUNK, nnz);

    if (threadIdx.x < R_REL) cnt[threadIdx.x] = 0;
    __syncthreads();
    for (int e = start + threadIdx.x; e < end; e += blockDim.x)
        atomicAdd(&cnt[(unsigned)rows[e] / N_NODES], 1u);
    __syncthreads();
    if (threadIdx.x < R_REL) {
        base[threadIdx.x] = atomicAdd(&g_cursor[threadIdx.x], cnt[threadIdx.x]);
        cnt[threadIdx.x] = 0;
    }
    __syncthreads();
    for (int e = start + threadIdx.x; e < end; e += blockDim.x) {
        unsigned row = (unsigned)rows[e];
        unsigned r = row / N_NODES;
        unsigned n = row - r * N_NODES;
        unsigned pos = base[r] + atomicAdd(&cnt[r], 1u);
        g_nm[pos] = (n << 16) | (unsigned)cols[e];
        g_v[pos]  = vals[e];
        g_r[pos]  = (unsigned char)r;
    }
}

__global__ void relu_bias_kernel(const float* __restrict__ bias1) {
    int idx = blockIdx.x * blockDim.x + threadIdx.x;
    const int n4 = N_NODES * E_DIM / 4;
    if (idx < n4) {
        float4* h4 = (float4*)g_h1;
        const float4* b4 = (const float4*)bias1;
        float4 v = h4[idx];
        float4 b = b4[idx & (E_DIM / 4 - 1)];
        v.x = fmaxf(v.x + b.x, 0.f);
        v.y = fmaxf(v.y + b.y, 0.f);
        v.z = fmaxf(v.z + b.z, 0.f);
        v.w = fmaxf(v.w + b.w, 0.f);
        h4[idx] = v;
    }
}

// ---------------------------------------------------------------------------
// Layer 1, quad layout: 4 lanes per edge, 8 edges per warp.
// lane q=lane>>2 owns edge slot; ql=lane&3 owns outputs e = ql*8..ql*8+7.
// x row (32 floats) split: lane holds floats ql*8..ql*8+7 (2 float4).
// w1 via broadcast conflict-free LDS.128 from smem (all 51 relations staged).
// ---------------------------------------------------------------------------
__global__ __launch_bounds__(512, 1)
void layer1_kernel(const float* __restrict__ x, int nnz) {
    extern __shared__ float sw[];                       // 52224 floats
    for (int i = threadIdx.x; i < R_REL * F_DIM * E_DIM; i += blockDim.x)
        sw[i] = g_w1[i];
    __syncthreads();

    const int lane = threadIdx.x & 31;
    const int ql   = lane & 3;
    const int qb   = lane & 28;                         // quad base lane
    int gw = (blockIdx.x * blockDim.x + threadIdx.x) >> 5;
    int nw = (gridDim.x * blockDim.x) >> 5;
    int ngroups = (nnz + 7) >> 3;                       // 8 edges per warp-iter

    for (int g = gw; g < ngroups; g += nw) {
        int idx = g * 8 + (lane >> 2);                  // this quad's edge
        int ce = idx < nnz ? idx : nnz - 1;
        unsigned nm = g_nm[ce];
        float v = idx < nnz ? g_v[ce] : 0.f;
        unsigned r = g_r[ce];
        unsigned n = nm >> 16;
        unsigned m = nm & 0xFFFFu;

        const float4* xr = (const float4*)(x + (size_t)m * F_DIM);
        float4 xa0 = xr[ql * 2];                        // floats ql*8 .. ql*8+3
        float4 xa1 = xr[ql * 2 + 1];                    // floats ql*8+4 .. ql*8+7

        const float* swr = sw + r * (F_DIM * E_DIM);

        ull acc0 = 0, acc1 = 0, acc2 = 0, acc3 = 0;
#pragma unroll
        for (int f = 0; f < F_DIM; f++) {
            float my = (f & 4) ? f4c(xa1, f & 3) : f4c(xa0, f & 3);
            float xf = __shfl_sync(0xffffffffu, my, qb + (f >> 3));
            ull xp = pack2(xf, xf);
            const ulonglong2* wf = (const ulonglong2*)(swr + f * E_DIM + ql * 8);
            ulonglong2 q0 = wf[0];                      // e = ql*8 .. +3
            ulonglong2 q1 = wf[1];                      // e = ql*8+4 .. +7
            acc0 = ffma2(xp, q0.x, acc0);
            acc1 = ffma2(xp, q0.y, acc1);
            acc2 = ffma2(xp, q1.x, acc2);
            acc3 = ffma2(xp, q1.y, acc3);
        }

        ull vp = pack2(v, v);
        float* hp = g_h1 + (size_t)n * E_DIM + ql * 8;
        float a0, a1, a2, a3;
        unpack2(fmul2(acc0, vp), a0, a1);
        unpack2(fmul2(acc1, vp), a2, a3);
        red_add_v4(hp, a0, a1, a2, a3);
        unpack2(fmul2(acc2, vp), a0, a1);
        unpack2(fmul2(acc3, vp), a2, a3);
        red_add_v4(hp + 4, a0, a1, a2, a3);
    }
}

// ---------------------------------------------------------------------------
// Layer 2, quad layout: lane ql owns outputs c = ql*4..ql*4+3.
// ---------------------------------------------------------------------------
__global__ __launch_bounds__(512, 1)
void layer2_kernel(float* __restrict__ out, int nnz) {
    extern __shared__ float sw[];                       // 26112 floats
    for (int i = threadIdx.x; i < R_REL * E_DIM * C_DIM; i += blockDim.x)
        sw[i] = g_w2[i];
    __syncthreads();

    const int lane = threadIdx.x & 31;
    const int ql   = lane & 3;
    const int qb   = lane & 28;
    int gw = (blockIdx.x * blockDim.x + threadIdx.x) >> 5;
    int nw = (gridDim.x * blockDim.x) >> 5;
    int ngroups = (nnz + 7) >> 3;

    for (int g = gw; g < ngroups; g += nw) {
        int idx = g * 8 + (lane >> 2);
        int ce = idx < nnz ? idx : nnz - 1;
        unsigned nm = g_nm[ce];
        float v = idx < nnz ? g_v[ce] : 0.f;
        unsigned r = g_r[ce];
        unsigned n = nm >> 16;
        unsigned m = nm & 0xFFFFu;

        const float4* hr = (const float4*)(g_h1 + (size_t)m * E_DIM);
        float4 ha0 = hr[ql * 2];
        float4 ha1 = hr[ql * 2 + 1];

        const float* swr = sw + r * (E_DIM * C_DIM);

        ull acc0 = 0, acc1 = 0;
#pragma unroll
        for (int f = 0; f < E_DIM; f++) {
            float my = (f & 4) ? f4c(ha1, f & 3) : f4c(ha0, f & 3);
            float hf = __shfl_sync(0xffffffffu, my, qb + (f >> 3));
            ull xp = pack2(hf, hf);
            const ulonglong2* wf = (const ulonglong2*)(swr + f * C_DIM + ql * 4);
            ulonglong2 q0 = wf[0];                      // c = ql*4 .. +3
            acc0 = ffma2(xp, q0.x, acc0);
            acc1 = ffma2(xp, q0.y, acc1);
        }

        ull vp = pack2(v, v);
        float* op = out + (size_t)n * C_DIM + ql * 4;
        float a0, a1, a2, a3;
        unpack2(fmul2(acc0, vp), a0, a1);
        unpack2(fmul2(acc1, vp), a2, a3);
        red_add_v4(op, a0, a1, a2, a3);
    }
}

// ---------------------------------------------------------------------------
extern "C" void kernel_launch(void* const* d_in, const int* in_sizes, int n_in,
                              void* d_out, int out_size) {
    const float* features = (const float*)d_in[0];
    const float* vals     = (const float*)d_in[1];
    const float* comps1   = (const float*)d_in[2];
    const float* bases1   = (const float*)d_in[3];
    const float* bias1    = (const float*)d_in[4];
    const float* comps2   = (const float*)d_in[5];
    const float* bases2   = (const float*)d_in[6];
    const float* bias2    = (const float*)d_in[7];
    const int*   rows     = (const int*)d_in[8];
    const int*   cols     = (const int*)d_in[9];
    float*       out      = (float*)d_out;
    const int    nnz      = in_sizes[8];

    const int smem1 = R_REL * F_DIM * E_DIM * (int)sizeof(float);  // 208896
    const int smem2 = R_REL * E_DIM * C_DIM * (int)sizeof(float);  // 104448
    static int attr_done = 0;
    if (!attr_done) {
        cudaFuncSetAttribute(layer1_kernel,
                             cudaFuncAttributeMaxDynamicSharedMemorySize, smem1);
        cudaFuncSetAttribute(layer2_kernel,
                             cudaFuncAttributeMaxDynamicSharedMemorySize, smem2);
        attr_done = 1;
    }

    // 1. weights + zero hist/done/h1
    compute_w_kernel<<<512, 256>>>(comps1, bases1, comps2, bases2);
    // 2. histogram + last-block scan + out=bias2
    hist_kernel<<<256, 256>>>(rows, nnz, out, bias2);
    // 3. bucket scatter (sorted-by-relation edge list)
    scatter_kernel<<<(nnz + SCATTER_CHUNK - 1) / SCATTER_CHUNK, 512>>>(
        rows, cols, vals, nnz);
    // 4. layer 1
    layer1_kernel<<<148, 512, smem1>>>(features, nnz);
    // 5. bias + relu
    relu_bias_kernel<<<(N_NODES * E_DIM / 4 + 255) / 256, 256>>>(bias1);
    // 6. layer 2
    layer2_kernel<<<148, 512, smem2>>>(out, nnz);
}